// round 17
// baseline (speedup 1.0000x reference)
#include <cuda_runtime.h>
#include <math.h>

#define BB 2048
#define NN 100
#define GG 100
#define EE 128

typedef unsigned long long ull;

__device__ __forceinline__ ull bcast2(float a) {
    ull r; asm("mov.b64 %0, {%1,%1};" : "=l"(r) : "f"(a)); return r;
}
__device__ __forceinline__ void unpack2(ull v, float& lo, float& hi) {
    asm("mov.b64 {%0,%1}, %2;" : "=f"(lo), "=f"(hi) : "l"(v));
}
__device__ __forceinline__ ull ffma2(ull a, ull b, ull c) {
    ull d; asm("fma.rn.f32x2 %0, %1, %2, %3;" : "=l"(d) : "l"(a), "l"(b), "l"(c));
    return d;
}
__device__ __forceinline__ ull fmul2(ull a, ull b) {
    ull d; asm("mul.rn.f32x2 %0, %1, %2;" : "=l"(d) : "l"(a), "l"(b)); return d;
}
__device__ __forceinline__ float tanh_acc(float x) {
    float ax = fabsf(x);
    float e = __expf(-2.0f * ax);
    float t = __fdividef(1.0f - e, 1.0f + e);
    return copysignf(t, x);
}

__device__ __forceinline__ void cp16(void* smem_ptr, const void* gptr) {
    unsigned s = (unsigned)__cvta_generic_to_shared(smem_ptr);
    asm volatile("cp.async.cg.shared.global [%0], [%1], 16;" :: "r"(s), "l"(gptr));
}
#define CP_COMMIT() asm volatile("cp.async.commit_group;")
#define CP_WAIT0()  asm volatile("cp.async.wait_group 0;")

// ---- global scratch ---------------------------------------------------------
__device__ float g_Wfl[EE * 128];
__device__ float g_qg[BB * 128];
__device__ float g_k[(size_t)BB * NN * EE];   // k -> later mh
__device__ float g_v[(size_t)BB * NN * EE];   // v
__device__ float g_q[(size_t)BB * NN * EE];   // q -> later attn

__global__ void prep_kernel(const float* __restrict__ Wqf,
                            const float* __restrict__ Wql) {
    int i = blockIdx.x * blockDim.x + threadIdx.x;
    if (i < EE * 128) g_Wfl[i] = Wqf[i] + Wql[i];
}

__global__ void qg_kernel(const float* __restrict__ enc,
                          const float* __restrict__ Wqg) {
    __shared__ float sG[EE];
    const int b = blockIdx.x, j = threadIdx.x;      // 128 threads
    const float* e0 = enc + (size_t)b * NN * EE + j;
    float s = 0.f;
    #pragma unroll 4
    for (int n = 0; n < NN; ++n) s += e0[n * EE];
    sG[j] = s * (1.0f / NN);
    __syncthreads();
    float a = 0.f;
    #pragma unroll 4
    for (int e = 0; e < EE; ++e) a += sG[e] * Wqg[e * 128 + j];
    g_qg[b * 128 + j] = a;
}

// ============================================================================
// Projection GEMMs: 1024 threads, 128 rows/CTA, warp = 4 rows x 4 cols.
// A staged via 32-row slab -> transposed into sAT[e][r] (stride 132).
// ============================================================================
#define SAT_FLOATS  (128 * 132)           // 16896
#define SW_FLOATS   (128 * 128)           // 16384
#define SLAB_FLOATS (32 * 132)            // 4224
#define KV_SMEM_FLOATS  (SAT_FLOATS + 2 * SW_FLOATS + SLAB_FLOATS)   // 53888
#define ONE_SMEM_FLOATS (SAT_FLOATS + SW_FLOATS + SLAB_FLOATS)       // 37504

__device__ __forceinline__ void stageW_1024(float* sW, const float* __restrict__ W,
                                            int tid) {
    #pragma unroll
    for (int k = 0; k < 4; ++k) {
        int i = tid + k * 1024;
        int r = i >> 5, c4 = (i & 31) * 4;
        cp16(sW + r * 128 + c4, W + r * 128 + c4);
    }
}

// stage 4 slabs of 32 rows, transposing each into sAT
__device__ __forceinline__ void stageA_T(float* sAT, float* sSLAB,
                                         const float* __restrict__ A,
                                         long long row0, int tid) {
    for (int slab = 0; slab < 4; ++slab) {
        {   // 1024 float4 = 32 rows x 128 cols
            int r = tid >> 5, c4 = (tid & 31) * 4;
            cp16(sSLAB + r * 132 + c4, A + (row0 + slab * 32 + r) * 128 + c4);
        }
        CP_COMMIT(); CP_WAIT0();
        __syncthreads();
        {   // transpose: thread -> (r, e4); scalar stores conflict-free
            int r = tid & 31, e4 = (tid >> 5) * 4;
            float4 v = *reinterpret_cast<const float4*>(sSLAB + r * 132 + e4);
            int rd = slab * 32 + r;
            sAT[(e4 + 0) * 132 + rd] = v.x;
            sAT[(e4 + 1) * 132 + rd] = v.y;
            sAT[(e4 + 2) * 132 + rd] = v.z;
            sAT[(e4 + 3) * 132 + rd] = v.w;
        }
        __syncthreads();
    }
}

// one compute pass: out[row0 + r][j] = sum_e AT[e][r] * W[e][j] (+bias)(+pervec)
__device__ __forceinline__ void pass4x4(const float* sAT, const float* sW,
                                        float* __restrict__ outp, long long row0,
                                        const float* __restrict__ bias,
                                        const float* __restrict__ pervec,
                                        int warp, int lane) {
    const int r0 = warp * 4;       // 32 warps x 4 rows = 128
    const int j0 = lane * 4;
    ull acc[2][4];
    #pragma unroll
    for (int p = 0; p < 2; ++p)
        #pragma unroll
        for (int c = 0; c < 4; ++c) acc[p][c] = 0ULL;

    #pragma unroll 4
    for (int e = 0; e < EE; ++e) {
        ulonglong2 A2 = *reinterpret_cast<const ulonglong2*>(sAT + e * 132 + r0);
        float4 w4 = *reinterpret_cast<const float4*>(sW + e * 128 + j0);
        ull w0 = bcast2(w4.x), w1 = bcast2(w4.y);
        ull w2 = bcast2(w4.z), w3 = bcast2(w4.w);
        acc[0][0] = ffma2(A2.x, w0, acc[0][0]); acc[0][1] = ffma2(A2.x, w1, acc[0][1]);
        acc[0][2] = ffma2(A2.x, w2, acc[0][2]); acc[0][3] = ffma2(A2.x, w3, acc[0][3]);
        acc[1][0] = ffma2(A2.y, w0, acc[1][0]); acc[1][1] = ffma2(A2.y, w1, acc[1][1]);
        acc[1][2] = ffma2(A2.y, w2, acc[1][2]); acc[1][3] = ffma2(A2.y, w3, acc[1][3]);
    }

    float4 badd = make_float4(0.f, 0.f, 0.f, 0.f);
    if (bias) badd = *reinterpret_cast<const float4*>(bias + j0);

    #pragma unroll
    for (int p = 0; p < 2; ++p) {
        const long long r = row0 + r0 + 2 * p;
        float4 lo4, hi4;
        unpack2(acc[p][0], lo4.x, hi4.x);
        unpack2(acc[p][1], lo4.y, hi4.y);
        unpack2(acc[p][2], lo4.z, hi4.z);
        unpack2(acc[p][3], lo4.w, hi4.w);
        lo4.x += badd.x; lo4.y += badd.y; lo4.z += badd.z; lo4.w += badd.w;
        hi4.x += badd.x; hi4.y += badd.y; hi4.z += badd.z; hi4.w += badd.w;
        if (pervec) {
            int b0 = (int)(r / 100), b1 = (int)((r + 1) / 100);
            float4 p0 = *reinterpret_cast<const float4*>(pervec + b0 * 128 + j0);
            float4 p1 = *reinterpret_cast<const float4*>(pervec + b1 * 128 + j0);
            lo4.x += p0.x; lo4.y += p0.y; lo4.z += p0.z; lo4.w += p0.w;
            hi4.x += p1.x; hi4.y += p1.y; hi4.z += p1.z; hi4.w += p1.w;
        }
        *reinterpret_cast<float4*>(outp + r * 128 + j0) = lo4;
        *reinterpret_cast<float4*>(outp + (r + 1) * 128 + j0) = hi4;
    }
}

// fused k+v projection: grid 1600
__global__ __launch_bounds__(1024, 1)
void proj_kv_kernel(const float* __restrict__ A,
                    const float* __restrict__ Wk, const float* __restrict__ Wv) {
    extern __shared__ float sm[];
    float* sAT   = sm;
    float* sW0   = sm + SAT_FLOATS;
    float* sW1   = sm + SAT_FLOATS + SW_FLOATS;
    float* sSLAB = sm + SAT_FLOATS + 2 * SW_FLOATS;
    const int tid  = threadIdx.x;
    const int lane = tid & 31;
    const int warp = tid >> 5;
    const long long row0 = (long long)blockIdx.x * 128;

    stageW_1024(sW0, Wk, tid);
    stageW_1024(sW1, Wv, tid);
    stageA_T(sAT, sSLAB, A, row0, tid);       // commits/waits cover W too

    pass4x4(sAT, sW0, g_k, row0, nullptr, nullptr, warp, lane);
    pass4x4(sAT, sW1, g_v, row0, nullptr, nullptr, warp, lane);
}

// single-W projection: grid 1600
__global__ __launch_bounds__(1024, 1)
void proj_one_kernel(const float* __restrict__ A, const float* __restrict__ W,
                     float* __restrict__ outp, const float* __restrict__ bias,
                     const float* __restrict__ pervec) {
    extern __shared__ float sm[];
    float* sAT   = sm;
    float* sW    = sm + SAT_FLOATS;
    float* sSLAB = sm + SAT_FLOATS + SW_FLOATS;
    const int tid  = threadIdx.x;
    const int lane = tid & 31;
    const int warp = tid >> 5;
    const long long row0 = (long long)blockIdx.x * 128;

    stageW_1024(sW, W, tid);
    stageA_T(sAT, sSLAB, A, row0, tid);

    pass4x4(sAT, sW, outp, row0, bias, pervec, warp, lane);
}

// ---- attention: grid (2048, 2) head-halves, 512 threads, 2 CTA/SM ----------
#define ATTN_SMEM_FLOATS (6800 + 6800 + 10000)   // sK, sV, sM
__global__ __launch_bounds__(512, 2)
void attn_kernel(const float* __restrict__ maskp) {
    extern __shared__ float sm[];
    float* sK = sm;            // [100][68]
    float* sV = sm + 6800;
    float* sM = sm + 13600;    // maskT [n][g]
    const int b    = blockIdx.x;
    const int half = blockIdx.y;
    const int tid  = threadIdx.x;
    const size_t rbase = (size_t)b * NN * EE + half * 64;

    for (int idx = tid; idx < NN * 16; idx += 512) {
        int n = idx >> 4, c4 = (idx & 15) * 4;
        *reinterpret_cast<float4*>(sK + n * 68 + c4) =
            *reinterpret_cast<const float4*>(g_k + rbase + (size_t)n * 128 + c4);
        *reinterpret_cast<float4*>(sV + n * 68 + c4) =
            *reinterpret_cast<const float4*>(g_v + rbase + (size_t)n * 128 + c4);
    }
    for (int idx = tid; idx < (GG * NN) / 4; idx += 512) {
        int g = idx / 25, n4 = (idx % 25) * 4;
        float4 mv = *reinterpret_cast<const float4*>(
            maskp + (size_t)b * GG * NN + g * NN + n4);
        sM[(n4 + 0) * 100 + g] = mv.x;
        sM[(n4 + 1) * 100 + g] = mv.y;
        sM[(n4 + 2) * 100 + g] = mv.z;
        sM[(n4 + 3) * 100 + g] = mv.w;
    }

    const int g  = tid & 127;
    const int hl = tid >> 7;
    const int c0 = hl * 16;
    const bool act = (g < GG);
    ull q2[8];
    if (act) {
        const float* qp = g_q + rbase + (size_t)g * 128 + c0;
        #pragma unroll
        for (int j = 0; j < 8; ++j)
            q2[j] = *reinterpret_cast<const ull*>(qp + 2 * j);
    }
    __syncthreads();

    if (act) {
        ull acc2[8];
        #pragma unroll
        for (int j = 0; j < 8; ++j) acc2[j] = 0ULL;
        float m = -1e30f, l = 0.f;
        const float* kb = sK + c0;
        const float* vb = sV + c0;
        for (int n = 0; n < NN; ++n) {
            const ulonglong2* kp = reinterpret_cast<const ulonglong2*>(kb + n * 68);
            ulonglong2 k0 = kp[0], k1 = kp[1], k2 = kp[2], k3 = kp[3];
            ull sa = 0ULL, sb = 0ULL;
            sa = ffma2(q2[0], k0.x, sa); sb = ffma2(q2[1], k0.y, sb);
            sa = ffma2(q2[2], k1.x, sa); sb = ffma2(q2[3], k1.y, sb);
            sa = ffma2(q2[4], k2.x, sa); sb = ffma2(q2[5], k2.y, sb);
            sa = ffma2(q2[6], k3.x, sa); sb = ffma2(q2[7], k3.y, sb);
            float x0, x1, y0, y1;
            unpack2(sa, x0, x1); unpack2(sb, y0, y1);
            float s = ((x0 + y0) + (x1 + y1)) * 0.25f + sM[n * 100 + g];
            const ulonglong2* vp = reinterpret_cast<const ulonglong2*>(vb + n * 68);
            ulonglong2 v0 = vp[0], v1 = vp[1], v2 = vp[2], v3 = vp[3];
            float mn = fmaxf(m, s);
            float c  = __expf(m - mn);
            float p  = __expf(s - mn);
            l = l * c + p;
            m = mn;
            ull cc = bcast2(c), pp = bcast2(p);
            acc2[0] = ffma2(acc2[0], cc, fmul2(v0.x, pp));
            acc2[1] = ffma2(acc2[1], cc, fmul2(v0.y, pp));
            acc2[2] = ffma2(acc2[2], cc, fmul2(v1.x, pp));
            acc2[3] = ffma2(acc2[3], cc, fmul2(v1.y, pp));
            acc2[4] = ffma2(acc2[4], cc, fmul2(v2.x, pp));
            acc2[5] = ffma2(acc2[5], cc, fmul2(v2.y, pp));
            acc2[6] = ffma2(acc2[6], cc, fmul2(v3.x, pp));
            acc2[7] = ffma2(acc2[7], cc, fmul2(v3.y, pp));
        }
        const float rl = __fdividef(1.f, l);
        float* dst = g_q + rbase + (size_t)g * 128 + c0;   // attn overwrites q
        #pragma unroll
        for (int j = 0; j < 4; ++j) {
            float4 o;
            unpack2(acc2[2 * j + 0], o.x, o.y);
            unpack2(acc2[2 * j + 1], o.z, o.w);
            o.x *= rl; o.y *= rl; o.z *= rl; o.w *= rl;
            *reinterpret_cast<float4*>(dst + 4 * j) = o;
        }
    }
}

// ---- pointer scores + masked softmax ---------------------------------------
#define PTR_SMEM_FLOATS (13312 + 13312 + 10400)   // sMT, sET, sS
__global__ __launch_bounds__(1024, 1)
void pointer_kernel(const float* __restrict__ enc, const float* __restrict__ maskp,
                    float* __restrict__ outp) {
    extern __shared__ float sm[];
    float* sMT = sm;            // mhT [128][104]
    float* sET = sm + 13312;    // encT [128][104]
    float* sS  = sm + 26624;    // S [100][104]
    const int b    = blockIdx.x;
    const int tid  = threadIdx.x;
    const int lane = tid & 31;
    const int warp = tid >> 5;

    for (int idx = tid; idx < NN * 32; idx += 1024) {
        int r = idx >> 5, e4 = (idx & 31) * 4;
        float4 mh4 = *reinterpret_cast<const float4*>(
            g_k + ((size_t)b * NN + r) * 128 + e4);          // mh lives in g_k
        sMT[(e4 + 0) * 104 + r] = mh4.x;
        sMT[(e4 + 1) * 104 + r] = mh4.y;
        sMT[(e4 + 2) * 104 + r] = mh4.z;
        sMT[(e4 + 3) * 104 + r] = mh4.w;
        float4 ev = *reinterpret_cast<const float4*>(
            enc + ((size_t)b * NN + r) * 128 + e4);
        sET[(e4 + 0) * 104 + r] = ev.x;
        sET[(e4 + 1) * 104 + r] = ev.y;
        sET[(e4 + 2) * 104 + r] = ev.z;
        sET[(e4 + 3) * 104 + r] = ev.w;
    }
    __syncthreads();

    if (warp < 25 && lane < 25) {
        const int g0 = warp * 4;
        const int n0 = lane * 4;
        ull acc[2][4];
        #pragma unroll
        for (int i = 0; i < 2; ++i)
            #pragma unroll
            for (int c = 0; c < 4; ++c) acc[i][c] = 0ULL;
        #pragma unroll 4
        for (int e = 0; e < EE; ++e) {
            ull a0 = *reinterpret_cast<const ull*>(sMT + e * 104 + g0);
            ull a1 = *reinterpret_cast<const ull*>(sMT + e * 104 + g0 + 2);
            float4 b4 = *reinterpret_cast<const float4*>(sET + e * 104 + n0);
            ull w0 = bcast2(b4.x), w1 = bcast2(b4.y);
            ull w2 = bcast2(b4.z), w3 = bcast2(b4.w);
            acc[0][0] = ffma2(a0, w0, acc[0][0]); acc[0][1] = ffma2(a0, w1, acc[0][1]);
            acc[0][2] = ffma2(a0, w2, acc[0][2]); acc[0][3] = ffma2(a0, w3, acc[0][3]);
            acc[1][0] = ffma2(a1, w0, acc[1][0]); acc[1][1] = ffma2(a1, w1, acc[1][1]);
            acc[1][2] = ffma2(a1, w2, acc[1][2]); acc[1][3] = ffma2(a1, w3, acc[1][3]);
        }
        const float rsE = 0.08838834764831845f;   // 1/sqrt(128)
        #pragma unroll
        for (int r = 0; r < 4; ++r) {
            float4 o;
            float lo, hi;
            unpack2(acc[r >> 1][0], lo, hi); o.x = 10.f * tanh_acc(((r & 1) ? hi : lo) * rsE);
            unpack2(acc[r >> 1][1], lo, hi); o.y = 10.f * tanh_acc(((r & 1) ? hi : lo) * rsE);
            unpack2(acc[r >> 1][2], lo, hi); o.z = 10.f * tanh_acc(((r & 1) ? hi : lo) * rsE);
            unpack2(acc[r >> 1][3], lo, hi); o.w = 10.f * tanh_acc(((r & 1) ? hi : lo) * rsE);
            *reinterpret_cast<float4*>(sS + (g0 + r) * 104 + n0) = o;
        }
    }
    __syncthreads();

    const float* maskB = maskp + (size_t)b * GG * NN;
    float*       outB  = outp + (size_t)b * GG * NN;
    for (int gr = warp; gr < GG; gr += 32) {
        float v[4];
        float mx = -1e30f;
        #pragma unroll
        for (int r = 0; r < 4; ++r) {
            const int n = lane + r * 32;
            float x = -1e30f;
            if (n < NN) x = sS[gr * 104 + n] + maskB[gr * NN + n];
            v[r] = x;
            mx = fmaxf(mx, x);
        }
        #pragma unroll
        for (int o = 16; o > 0; o >>= 1) mx = fmaxf(mx, __shfl_xor_sync(~0u, mx, o));
        float sum = 0.f;
        #pragma unroll
        for (int r = 0; r < 4; ++r) {
            const int n = lane + r * 32;
            float e = (n < NN) ? __expf(v[r] - mx) : 0.f;
            v[r] = e;
            sum += e;
        }
        #pragma unroll
        for (int o = 16; o > 0; o >>= 1) sum += __shfl_xor_sync(~0u, sum, o);
        const float inv = __fdividef(1.f, sum);
        #pragma unroll
        for (int r = 0; r < 4; ++r) {
            const int n = lane + r * 32;
            if (n < NN) outB[gr * NN + n] = v[r] * inv;
        }
    }
}

extern "C" void kernel_launch(void* const* d_in, const int* in_sizes, int n_in,
                              void* d_out, int out_size) {
    const float* enc  = (const float*)d_in[0];
    const float* last = (const float*)d_in[1];
    const float* mask = (const float*)d_in[2];
    const float* Wqg  = (const float*)d_in[3];
    const float* Wqf  = (const float*)d_in[4];
    const float* Wql  = (const float*)d_in[5];
    const float* Wk   = (const float*)d_in[6];
    const float* Wv   = (const float*)d_in[7];
    const float* Wc   = (const float*)d_in[8];
    const float* bc   = (const float*)d_in[9];
    float* out = (float*)d_out;

    static int configured = 0;
    if (!configured) {
        cudaFuncSetAttribute(proj_kv_kernel, cudaFuncAttributeMaxDynamicSharedMemorySize,
                             KV_SMEM_FLOATS * 4);
        cudaFuncSetAttribute(proj_one_kernel, cudaFuncAttributeMaxDynamicSharedMemorySize,
                             ONE_SMEM_FLOATS * 4);
        cudaFuncSetAttribute(attn_kernel, cudaFuncAttributeMaxDynamicSharedMemorySize,
                             ATTN_SMEM_FLOATS * 4);
        cudaFuncSetAttribute(pointer_kernel, cudaFuncAttributeMaxDynamicSharedMemorySize,
                             PTR_SMEM_FLOATS * 4);
        configured = 1;
    }

    float* gk;  cudaGetSymbolAddress((void**)&gk, g_k);
    float* gq;  cudaGetSymbolAddress((void**)&gq, g_q);
    float* gqg; cudaGetSymbolAddress((void**)&gqg, g_qg);
    float* gwfl; cudaGetSymbolAddress((void**)&gwfl, g_Wfl);

    prep_kernel<<<(EE * 128 + 255) / 256, 256>>>(Wqf, Wql);
    qg_kernel<<<BB, 128>>>(enc, Wqg);

    proj_kv_kernel<<<1600, 1024, KV_SMEM_FLOATS * 4>>>(enc, Wk, Wv);
    proj_one_kernel<<<1600, 1024, ONE_SMEM_FLOATS * 4>>>(last, gwfl, gq, nullptr, gqg);

    attn_kernel<<<dim3(BB, 2), 512, ATTN_SMEM_FLOATS * 4>>>(mask);

    proj_one_kernel<<<1600, 1024, ONE_SMEM_FLOATS * 4>>>(gq, Wc, gk, bc, nullptr);

    pointer_kernel<<<BB, 1024, PTR_SMEM_FLOATS * 4>>>(enc, mask, out);
}